// round 1
// baseline (speedup 1.0000x reference)
#include <cuda_runtime.h>
#include <math_constants.h>

// Problem constants (from reference setup_inputs)
#define BATCH   8
#define NPTS    4096
#define NDIM    3

#define THREADS 128
#define PTS     4                    // x points per thread (register blocked)
#define XCHUNK  (THREADS * PTS)      // 512 points per block
#define NXCH    (NPTS / XCHUNK)      // 8
#define YCHUNK  1024                 // y points per block (fits shared as float4: 16KB)
#define NYCH    (NPTS / YCHUNK)      // 4

// Scratch: per-point min squared distance, stored as uint bit pattern
// (valid order-preserving encoding since all values are >= 0).
// Layout: [dir][batch][point], dir 0 = x->y, dir 1 = y->x.
__device__ unsigned int g_minsq[2 * BATCH * NPTS];

__global__ void chamfer_init_kernel() {
    int i = blockIdx.x * blockDim.x + threadIdx.x;
    if (i < 2 * BATCH * NPTS) g_minsq[i] = 0x7F800000u;  // +inf
}

__global__ __launch_bounds__(THREADS)
void chamfer_pairs_kernel(const float* __restrict__ x,
                          const float* __restrict__ y) {
    const int dir = blockIdx.z >> 3;   // 0..1
    const int b   = blockIdx.z & 7;    // 0..7

    const float* __restrict__ P = dir ? y : x;   // points we take the min FOR
    const float* __restrict__ Q = dir ? x : y;   // points we take the min OVER

    __shared__ float4 sq[YCHUNK];

    // Cooperative load of this block's y-chunk into shared (float4-padded
    // so the inner loop is a single broadcast LDS.128 per j).
    const float* __restrict__ Qb = Q + ((size_t)b * NPTS + (size_t)blockIdx.y * YCHUNK) * NDIM;
    for (int j = threadIdx.x; j < YCHUNK; j += THREADS) {
        float qx = Qb[j * 3 + 0];
        float qy = Qb[j * 3 + 1];
        float qz = Qb[j * 3 + 2];
        sq[j] = make_float4(qx, qy, qz, 0.0f);
    }
    __syncthreads();

    // Register-block PTS x-points per thread.
    const int pbase = blockIdx.x * XCHUNK + threadIdx.x;
    const float* __restrict__ Pb = P + (size_t)b * NPTS * NDIM;

    float px[PTS], py[PTS], pz[PTS], mn[PTS];
#pragma unroll
    for (int p = 0; p < PTS; p++) {
        int idx = pbase + p * THREADS;
        px[p] = Pb[idx * 3 + 0];
        py[p] = Pb[idx * 3 + 1];
        pz[p] = Pb[idx * 3 + 2];
        mn[p] = CUDART_INF_F;
    }

    // Main loop: 1 broadcast LDS.128 feeds 4 points x 6 fma-pipe instrs.
#pragma unroll 4
    for (int j = 0; j < YCHUNK; j++) {
        float4 q = sq[j];
#pragma unroll
        for (int p = 0; p < PTS; p++) {
            float dx = px[p] - q.x;
            float dy = py[p] - q.y;
            float dz = pz[p] - q.z;
            float d  = fmaf(dz, dz, fmaf(dy, dy, dx * dx));
            mn[p] = fminf(mn[p], d);
        }
    }

    // Combine partial mins across y-chunk blocks.
    unsigned int* gm = g_minsq + ((size_t)dir * BATCH + b) * NPTS;
#pragma unroll
    for (int p = 0; p < PTS; p++) {
        atomicMin(&gm[pbase + p * THREADS], __float_as_uint(mn[p]));
    }
}

__global__ __launch_bounds__(1024)
void chamfer_reduce_kernel(float* __restrict__ out) {
    // out = (sum over all 2*B*N entries of sqrt(minsq)) / (B*N)
    // because chamfer = mean_b( mean_n min_x2y + mean_m min_y2x ) and N == M.
    __shared__ float ssum[1024];
    float s = 0.0f;
    for (int i = threadIdx.x; i < 2 * BATCH * NPTS; i += 1024) {
        s += sqrtf(__uint_as_float(g_minsq[i]));
    }
    ssum[threadIdx.x] = s;
    __syncthreads();
    for (int off = 512; off > 0; off >>= 1) {
        if (threadIdx.x < off) ssum[threadIdx.x] += ssum[threadIdx.x + off];
        __syncthreads();
    }
    if (threadIdx.x == 0) out[0] = ssum[0] / (float)(BATCH * NPTS);
}

extern "C" void kernel_launch(void* const* d_in, const int* in_sizes, int n_in,
                              void* d_out, int out_size) {
    const float* x = (const float*)d_in[0];
    const float* y = (const float*)d_in[1];
    float* out = (float*)d_out;

    chamfer_init_kernel<<<(2 * BATCH * NPTS + 255) / 256, 256>>>();

    dim3 grid(NXCH, NYCH, 2 * BATCH);   // 8 x 4 x 16 = 512 blocks
    chamfer_pairs_kernel<<<grid, THREADS>>>(x, y);

    chamfer_reduce_kernel<<<1, 1024>>>(out);
}

// round 2
// speedup vs baseline: 1.4374x; 1.4374x over previous
#include <cuda_runtime.h>
#include <math_constants.h>

// Problem constants (from reference setup_inputs)
#define BATCH   8
#define NPTS    4096
#define NDIM    3

#define THREADS 128
#define PTS     4                    // x points per thread (2 packed f32x2 pairs)
#define XCHUNK  (THREADS * PTS)      // 512
#define NXCH    (NPTS / XCHUNK)      // 8
#define YCHUNK  512                  // q points per block tile
#define NYCH    (NPTS / YCHUNK)      // 8

// Per-point min of r = (|q|^2)/2 - p.q + (|p|^2)/2  (= d^2/2 after min),
// stored as monotone-mapped uint keys (safe for negative floats).
// Layout: [dir][batch][point].
__device__ unsigned int g_minkey[2 * BATCH * NPTS];

__device__ __forceinline__ unsigned long long ffma2(unsigned long long a,
                                                    unsigned long long b,
                                                    unsigned long long c) {
    unsigned long long d;
    asm("fma.rn.f32x2 %0, %1, %2, %3;" : "=l"(d) : "l"(a), "l"(b), "l"(c));
    return d;
}

__device__ __forceinline__ unsigned long long pack2(float lo, float hi) {
    unsigned long long r;
    asm("mov.b64 %0, {%1, %2};" : "=l"(r) : "f"(lo), "f"(hi));
    return r;
}

__device__ __forceinline__ unsigned int fkey(float f) {
    unsigned int u = __float_as_uint(f);
    return u ^ (((unsigned int)((int)u >> 31)) | 0x80000000u);
}

__global__ void chamfer_init_kernel() {
    int i = blockIdx.x * blockDim.x + threadIdx.x;
    if (i < 2 * BATCH * NPTS) g_minkey[i] = 0xFF800000u;  // fkey(+inf)
}

__global__ __launch_bounds__(THREADS)
void chamfer_pairs_kernel(const float* __restrict__ x,
                          const float* __restrict__ y) {
    const int dir = blockIdx.z >> 3;   // 0..1
    const int b   = blockIdx.z & 7;    // 0..7

    const float* __restrict__ P = dir ? y : x;   // points we take the min FOR
    const float* __restrict__ Q = dir ? x : y;   // points we take the min OVER

    // Shared tile: per q point, 4 duplicated components:
    // {qx,qx}, {qy,qy}, {qz,qz}, {hq,hq} with hq = |q|^2 / 2.  32 B per point.
    __shared__ unsigned long long sq[YCHUNK * 4];

    const float* __restrict__ Qb =
        Q + ((size_t)b * NPTS + (size_t)blockIdx.y * YCHUNK) * NDIM;
    for (int j = threadIdx.x; j < YCHUNK; j += THREADS) {
        float qx = Qb[j * 3 + 0];
        float qy = Qb[j * 3 + 1];
        float qz = Qb[j * 3 + 2];
        float hq = 0.5f * fmaf(qz, qz, fmaf(qy, qy, qx * qx));
        sq[j * 4 + 0] = pack2(qx, qx);
        sq[j * 4 + 1] = pack2(qy, qy);
        sq[j * 4 + 2] = pack2(qz, qz);
        sq[j * 4 + 3] = pack2(hq, hq);
    }
    __syncthreads();

    // Register setup: PTS points, packed in pairs as negated components.
    const int pbase = blockIdx.x * XCHUNK + threadIdx.x;
    const float* __restrict__ Pb = P + (size_t)b * NPTS * NDIM;

    float px[PTS], py[PTS], pz[PTS], hp[PTS];
#pragma unroll
    for (int p = 0; p < PTS; p++) {
        int idx = pbase + p * THREADS;
        px[p] = Pb[idx * 3 + 0];
        py[p] = Pb[idx * 3 + 1];
        pz[p] = Pb[idx * 3 + 2];
        hp[p] = 0.5f * fmaf(pz[p], pz[p], fmaf(py[p], py[p], px[p] * px[p]));
    }
    unsigned long long npx01 = pack2(-px[0], -px[1]);
    unsigned long long npy01 = pack2(-py[0], -py[1]);
    unsigned long long npz01 = pack2(-pz[0], -pz[1]);
    unsigned long long npx23 = pack2(-px[2], -px[3]);
    unsigned long long npy23 = pack2(-py[2], -py[3]);
    unsigned long long npz23 = pack2(-pz[2], -pz[3]);

    float mn[PTS];
#pragma unroll
    for (int p = 0; p < PTS; p++) mn[p] = CUDART_INF_F;

    const ulonglong2* __restrict__ sp = (const ulonglong2*)sq;

    // Inner loop: 2x LDS.128 + 6x FFMA2 + 4x FMNMX per j for 4 pairs.
#pragma unroll 4
    for (int j = 0; j < YCHUNK; j++) {
        ulonglong2 A = sp[2 * j + 0];   // .x = {qx,qx}, .y = {qy,qy}
        ulonglong2 B = sp[2 * j + 1];   // .x = {qz,qz}, .y = {hq,hq}

        unsigned long long r01 = ffma2(npz01, B.x, B.y);
        r01 = ffma2(npy01, A.y, r01);
        r01 = ffma2(npx01, A.x, r01);

        unsigned long long r23 = ffma2(npz23, B.x, B.y);
        r23 = ffma2(npy23, A.y, r23);
        r23 = ffma2(npx23, A.x, r23);

        mn[0] = fminf(mn[0], __uint_as_float((unsigned int)r01));
        mn[1] = fminf(mn[1], __uint_as_float((unsigned int)(r01 >> 32)));
        mn[2] = fminf(mn[2], __uint_as_float((unsigned int)r23));
        mn[3] = fminf(mn[3], __uint_as_float((unsigned int)(r23 >> 32)));
    }

    // Combine across y-chunk blocks: value = min(hq - p.q) + hp = d^2/2.
    unsigned int* gm = g_minkey + ((size_t)dir * BATCH + b) * NPTS;
#pragma unroll
    for (int p = 0; p < PTS; p++) {
        atomicMin(&gm[pbase + p * THREADS], fkey(mn[p] + hp[p]));
    }
}

__global__ __launch_bounds__(1024)
void chamfer_reduce_kernel(float* __restrict__ out) {
    __shared__ float ssum[1024];
    float s = 0.0f;
    for (int i = threadIdx.x; i < 2 * BATCH * NPTS; i += 1024) {
        unsigned int k = g_minkey[i];
        unsigned int u = (k & 0x80000000u) ? (k ^ 0x80000000u) : ~k;
        float halfd2 = __uint_as_float(u);
        s += sqrtf(fmaxf(2.0f * halfd2, 0.0f));
    }
    ssum[threadIdx.x] = s;
    __syncthreads();
    for (int off = 512; off > 0; off >>= 1) {
        if (threadIdx.x < off) ssum[threadIdx.x] += ssum[threadIdx.x + off];
        __syncthreads();
    }
    if (threadIdx.x == 0) out[0] = ssum[0] / (float)(BATCH * NPTS);
}

extern "C" void kernel_launch(void* const* d_in, const int* in_sizes, int n_in,
                              void* d_out, int out_size) {
    const float* x = (const float*)d_in[0];
    const float* y = (const float*)d_in[1];
    float* out = (float*)d_out;

    chamfer_init_kernel<<<(2 * BATCH * NPTS + 255) / 256, 256>>>();

    dim3 grid(NXCH, NYCH, 2 * BATCH);   // 8 x 8 x 16 = 1024 blocks
    chamfer_pairs_kernel<<<grid, THREADS>>>(x, y);

    chamfer_reduce_kernel<<<1, 1024>>>(out);
}